// round 12
// baseline (speedup 1.0000x reference)
#include <cuda_runtime.h>
#include <cstdint>

// SliceLSTM persistent kernel, round 11 = R10 + cp.async FIFO fix,
// full-width P3, fence removal.
// 128 CTAs x 256 threads, clusters of 4 = (gate, K-chunk), rank = tile.

#define NCTA 128
#define NTHR 256

typedef unsigned long long u64;

// shared layout (float offsets)
#define OFF_W1  0         // 192 x 16
#define OFF_B1  3072      // 16
#define OFF_W2  3088      // 64 x 128
#define OFF_X   11280     // [2 parity][64 b][68]  (x, b-major)
#define LDXR    68
#define XPAR    (64 * LDXR)
#define OFF_H   19984     // [64 b][132]           (h, b-major)
#define LDHR    132
#define OFF_ACT 28432     // [2 parity][64 c][68]  (act, k-major)
#define LDA     68
#define APAR    (64 * LDA)
#define SMEM_FLOATS 37136
#define SMEM_BYTES  (SMEM_FLOATS * 4)   // 145.1KB -> 1 CTA/SM

__device__ float g_hbuf[2][64 * 512];           // [parity][b][c]
__device__ float g_part[2][NCTA * 64 * 128];    // [parity][cta][b][cl]
__device__ unsigned g_pcnt[4 * 64];             // per tile, 256B apart
__device__ unsigned g_hcnt[4 * 64];

static __device__ __forceinline__ u64 pk2(float v) {
    u64 r; asm("mov.b64 %0, {%1, %1};" : "=l"(r) : "f"(v)); return r;
}
static __device__ __forceinline__ void unp2(u64 v, float& lo, float& hi) {
    asm("mov.b64 {%0, %1}, %2;" : "=f"(lo), "=f"(hi) : "l"(v));
}
static __device__ __forceinline__ void fma2(u64& d, u64 a, u64 b) {
    asm("fma.rn.f32x2 %0, %1, %2, %0;" : "+l"(d) : "l"(a), "l"(b));
}
static __device__ __forceinline__ float sigf(float x)  { return 1.0f / (1.0f + __expf(-x)); }
static __device__ __forceinline__ float tanhe(float x) {
    float e = __expf(2.0f * x);
    return 1.0f - 2.0f / (e + 1.0f);
}
static __device__ __forceinline__ unsigned ldacq(const unsigned* p) {
    unsigned v;
    asm volatile("ld.acquire.gpu.global.u32 %0, [%1];" : "=r"(v) : "l"(p) : "memory");
    return v;
}
static __device__ __forceinline__ void redrel(unsigned* p) {
    asm volatile("red.release.gpu.global.add.u32 [%0], 1;" :: "l"(p) : "memory");
}
static __device__ __forceinline__ uint32_t smem_u32(const void* p) {
    uint32_t a;
    asm("{ .reg .u64 t; cvta.to.shared.u64 t, %1; cvt.u32.u64 %0, t; }" : "=r"(a) : "l"(p));
    return a;
}
static __device__ __forceinline__ uint32_t mapa_rank(uint32_t addr, int rank) {
    uint32_t r;
    asm("mapa.shared::cluster.u32 %0, %1, %2;" : "=r"(r) : "r"(addr), "r"(rank));
    return r;
}
static __device__ __forceinline__ void st_cluster(uint32_t addr, float v) {
    asm volatile("st.shared::cluster.f32 [%0], %1;" :: "r"(addr), "f"(v) : "memory");
}
static __device__ __forceinline__ void cpasync16(uint32_t dst, const float* src) {
    asm volatile("cp.async.cg.shared.global [%0], [%1], 16;" :: "r"(dst), "l"(src) : "memory");
}
#define CP_COMMIT() asm volatile("cp.async.commit_group;" ::: "memory")
#define CP_WAIT0()  asm volatile("cp.async.wait_group 0;" ::: "memory")
#define CP_WAIT1()  asm volatile("cp.async.wait_group 1;" ::: "memory")
#define CP_WAIT2()  asm volatile("cp.async.wait_group 2;" ::: "memory")
#define CARRIVE() asm volatile("barrier.cluster.arrive.aligned;" ::: "memory")
#define CWAIT()   asm volatile("barrier.cluster.wait.aligned;" ::: "memory")

__global__ void zero_kernel() {
    int i = blockIdx.x * blockDim.x + threadIdx.x;
    int n = blockDim.x * gridDim.x;
    for (int j = i; j < 64 * 512; j += n) g_hbuf[0][j] = 0.0f;
    for (int j = i; j < 4 * 64; j += n) { g_pcnt[j] = 0u; g_hcnt[j] = 0u; }
}

__global__ void __launch_bounds__(NTHR, 1) __cluster_dims__(4, 1, 1)
slstm_kernel(const float* __restrict__ x,       // (64, 512, 256)
             const float* __restrict__ Ws,      // (4, 64, 512)
             const float* __restrict__ Us,      // (4, 128, 512)
             const float* __restrict__ biases,  // (4, 512)
             const float* __restrict__ Wc,      // (512, 2048)
             const float* __restrict__ bc,      // (2048,)
             float* __restrict__ out)           // hseq | h_t | c_t
{
    extern __shared__ float sm[];
    float* sW1  = sm + OFF_W1;
    float* sB1  = sm + OFF_B1;
    float* sW2  = sm + OFF_W2;
    float* sX   = sm + OFF_X;
    float* sH   = sm + OFF_H;
    float* sAct = sm + OFF_ACT;

    const int tid  = threadIdx.x;
    const int cta  = blockIdx.x;
    const int rank = cta & 3;
    const int clu  = cta >> 2;        // 0..31
    const int g2   = clu >> 3;        // gate
    const int kc   = clu & 7;         // connector K-chunk
    const int s1   = kc >> 1;         // input slice
    const int wcol0 = g2 * 128 + (kc & 1) * 64 + rank * 16;

    // P1 role: 1 batch x 4 cols per thread
    const int pab = tid >> 2;
    const int pac = tid & 3;
    // P2 role: 4 batches x 8 cols per thread
    const int b20 = (tid & 15) * 4;
    const int cg2 = tid >> 4;          // 0..15
    // P3 role: one (batch, col) per thread
    const int p3b  = clu * 2 + (tid >> 7);
    const int p3c  = tid & 127;
    const int colg = rank * 128 + p3c;

    // ---- persistent weights ----
    for (int i = tid; i < 192 * 16; i += NTHR) {
        int k = i >> 4, c = i & 15;
        sW1[i] = (k < 64) ? Ws[s1 * (64 * 512) + k * 512 + wcol0 + c]
                          : Us[s1 * (128 * 512) + (k - 64) * 512 + wcol0 + c];
    }
    if (tid < 16) sB1[tid] = biases[s1 * 512 + wcol0 + tid];
    for (int i = tid; i < 64 * 128; i += NTHR) {
        int k = i >> 7, c = i & 127;
        sW2[k * 128 + c] = Wc[(kc * 64 + k) * 2048 + g2 * 512 + rank * 128 + c];
    }

    // P3 biases + per-thread scalar state
    const float bci = bc[colg];
    const float bcf = bc[512 + colg];
    const float bcg = bc[1024 + colg];
    const float bco = bc[1536 + colg];
    float creg = 0.0f, hlast = 0.0f;

    const uint32_t xs_u32  = smem_u32(sX);
    const uint32_t hs_u32  = smem_u32(sH);
    const uint32_t act_u32 = smem_u32(sAct);
    uint32_t peer[4];
    #pragma unroll
    for (int r = 0; r < 4; ++r) peer[r] = mapa_rank(act_u32, r);

    // stage x(t=0) into parity 0
    {
        #pragma unroll
        for (int j = 0; j < 4; ++j) {
            int lin = tid + 256 * j;
            int b = lin & 63, q = lin >> 6;
            cpasync16(xs_u32 + (b * LDXR + q * 4) * 4,
                      &x[b * (512 * 256) + s1 * 64 + q * 4]);
        }
        CP_COMMIT();
        CP_WAIT0();
    }
    __syncthreads();

    for (int t = 0; t < 512; ++t) {
        const int p  = t & 1;
        const int pn = p ^ 1;

        // --- (1) wait h-flag ---
        if (tid == 0) {
            const unsigned need = 32u * (unsigned)t;
            while (ldacq(&g_hcnt[s1 * 64]) < need) {}
        }
        __syncthreads();

        // --- (2) commit h group (older), then x(t+1) group (newer) ---
        {
            const float* hb = g_hbuf[p];
            #pragma unroll
            for (int j = 0; j < 8; ++j) {
                int lin = tid + 256 * j;
                int b = lin & 63, q = lin >> 6;
                cpasync16(hs_u32 + (b * LDHR + q * 4) * 4,
                          &hb[b * 512 + s1 * 128 + q * 4]);
            }
        }
        CP_COMMIT();
        if (t + 1 < 512) {
            #pragma unroll
            for (int j = 0; j < 4; ++j) {
                int lin = tid + 256 * j;
                int b = lin & 63, q = lin >> 6;
                cpasync16(xs_u32 + (pn * XPAR + b * LDXR + q * 4) * 4,
                          &x[b * (512 * 256) + (t + 1) * 256 + s1 * 64 + q * 4]);
            }
        }
        CP_COMMIT();           // (possibly empty group at t=511)

        // --- (3) x(t) resident; P1 x-part ---
        CP_WAIT2();
        __syncthreads();
        u64 acc0 = 0ULL, acc1 = 0ULL;
        {
            const float* ap = sX + p * XPAR + pab * LDXR;
            const float* wp = sW1 + pac * 4;
            #pragma unroll 8
            for (int k = 0; k < 64; ++k) {
                const ulonglong2 w = *reinterpret_cast<const ulonglong2*>(wp + k * 16);
                const u64 a = pk2(ap[k]);
                fma2(acc0, a, w.x);
                fma2(acc1, a, w.y);
            }
        }

        // --- (4) h resident; P1 h-part + activation ---
        CP_WAIT1();            // h retired; x(t+1) may stay in flight
        __syncthreads();
        float v0, v1, v2, v3;
        {
            const float* ap = sH + pab * LDHR;
            const float* wp = sW1 + pac * 4;
            #pragma unroll 8
            for (int k = 0; k < 128; ++k) {
                const ulonglong2 w = *reinterpret_cast<const ulonglong2*>(wp + (64 + k) * 16);
                const u64 a = pk2(ap[k]);
                fma2(acc0, a, w.x);
                fma2(acc1, a, w.y);
            }
            unp2(acc0, v0, v1);
            unp2(acc1, v2, v3);
            v0 += sB1[pac * 4 + 0];
            v1 += sB1[pac * 4 + 1];
            v2 += sB1[pac * 4 + 2];
            v3 += sB1[pac * 4 + 3];
            if (g2 == 2) { v0 = tanhe(v0); v1 = tanhe(v1); v2 = tanhe(v2); v3 = tanhe(v3); }
            else         { v0 = sigf(v0);  v1 = sigf(v1);  v2 = sigf(v2);  v3 = sigf(v3);  }
        }

        // --- (5) act publish local + remote, one cluster barrier ---
        {
            const int lc = rank * 16 + pac * 4;
            const int base = p * APAR + lc * LDA + pab;
            sAct[base]           = v0;
            sAct[base + LDA]     = v1;
            sAct[base + 2 * LDA] = v2;
            sAct[base + 3 * LDA] = v3;
            const uint32_t off = (uint32_t)base * 4;
            #pragma unroll
            for (int r = 0; r < 4; ++r) {
                if (r == rank) continue;
                const uint32_t ra = peer[r] + off;
                st_cluster(ra,               v0);
                st_cluster(ra + 4 * LDA,     v1);
                st_cluster(ra + 8 * LDA,     v2);
                st_cluster(ra + 12 * LDA,    v3);
            }
        }
        CARRIVE();
        CWAIT();

        // --- (6) P2 connector GEMM ---
        {
            u64 acc[4][4];
            #pragma unroll
            for (int i = 0; i < 4; ++i)
                #pragma unroll
                for (int j = 0; j < 4; ++j) acc[i][j] = 0ULL;
            const float* ab = sAct + p * APAR;
            const float* wb = sW2 + cg2 * 8;
            #pragma unroll 4
            for (int k = 0; k < 64; ++k) {
                const float4 a4 = *reinterpret_cast<const float4*>(&ab[k * LDA + b20]);
                const ulonglong2 wA = *reinterpret_cast<const ulonglong2*>(&wb[k * 128]);
                const ulonglong2 wB = *reinterpret_cast<const ulonglong2*>(&wb[k * 128 + 4]);
                const u64 a0 = pk2(a4.x);
                const u64 a1 = pk2(a4.y);
                const u64 a2 = pk2(a4.z);
                const u64 a3 = pk2(a4.w);
                fma2(acc[0][0], a0, wA.x); fma2(acc[0][1], a0, wA.y);
                fma2(acc[0][2], a0, wB.x); fma2(acc[0][3], a0, wB.y);
                fma2(acc[1][0], a1, wA.x); fma2(acc[1][1], a1, wA.y);
                fma2(acc[1][2], a1, wB.x); fma2(acc[1][3], a1, wB.y);
                fma2(acc[2][0], a2, wA.x); fma2(acc[2][1], a2, wA.y);
                fma2(acc[2][2], a2, wB.x); fma2(acc[2][3], a2, wB.y);
                fma2(acc[3][0], a3, wA.x); fma2(acc[3][1], a3, wA.y);
                fma2(acc[3][2], a3, wB.x); fma2(acc[3][3], a3, wB.y);
            }
            float* pp = g_part[p] + cta * 8192 + cg2 * 8;
            #pragma unroll
            for (int i = 0; i < 4; ++i) {
                float q0, q1, q2, q3, q4, q5, q6, q7;
                unp2(acc[i][0], q0, q1); unp2(acc[i][1], q2, q3);
                unp2(acc[i][2], q4, q5); unp2(acc[i][3], q6, q7);
                float4* d = reinterpret_cast<float4*>(pp + (b20 + i) * 128);
                __stcg(d,     make_float4(q0, q1, q2, q3));
                __stcg(d + 1, make_float4(q4, q5, q6, q7));
            }
        }
        __syncthreads();
        if (tid == 0) {
            redrel(&g_pcnt[rank * 64]);
            const unsigned need = 32u * (unsigned)(t + 1);
            while (ldacq(&g_pcnt[rank * 64]) < need) {}
        }
        __syncthreads();

        // --- (7) P3 on ALL 256 threads: one (b,c) each ---
        {
            float a0 = bci, a1 = bcf, a2 = bcg, a3 = bco;
            const float* gp = g_part[p] + p3b * 128 + p3c;
            #pragma unroll
            for (int q = 0; q < 8; ++q) {
                a0 += __ldcg(gp + (( 0 + q) * 4 + rank) * 8192);
                a1 += __ldcg(gp + (( 8 + q) * 4 + rank) * 8192);
                a2 += __ldcg(gp + ((16 + q) * 4 + rank) * 8192);
                a3 += __ldcg(gp + ((24 + q) * 4 + rank) * 8192);
            }
            const float iv = sigf(a0);
            const float fv = sigf(a1);
            const float gv = tanhe(a2);
            const float ov = sigf(a3);
            creg = fv * creg + iv * gv;
            const float hn = ov * tanhe(creg);
            hlast = hn;
            __stcg(&g_hbuf[pn][p3b * 512 + colg], hn);
            __syncthreads();
            if (tid == 0) redrel(&g_hcnt[rank * 64]);
            out[p3b * (512 * 512) + t * 512 + colg] = hn;
        }
    }

    out[16777216 + p3b * 512 + colg] = hlast;
    out[16777216 + 32768 + p3b * 512 + colg] = creg;
}

extern "C" void kernel_launch(void* const* d_in, const int* in_sizes, int n_in,
                              void* d_out, int out_size) {
    const float* x      = (const float*)d_in[0];
    const float* Ws     = (const float*)d_in[1];
    const float* Us     = (const float*)d_in[2];
    const float* biases = (const float*)d_in[3];
    const float* Wc     = (const float*)d_in[4];
    const float* bc     = (const float*)d_in[5];
    float* out = (float*)d_out;
    (void)in_sizes; (void)n_in; (void)out_size;

    zero_kernel<<<32, 256>>>();
    cudaFuncSetAttribute(slstm_kernel, cudaFuncAttributeMaxDynamicSharedMemorySize,
                         SMEM_BYTES);
    slstm_kernel<<<NCTA, NTHR, SMEM_BYTES>>>(x, Ws, Us, biases, Wc, bc, out);
}

// round 16
// speedup vs baseline: 1.0670x; 1.0670x over previous
#include <cuda_runtime.h>
#include <cstdint>

// SliceLSTM persistent kernel, round 13 = R12 with the act-publish byte-offset
// fix (one column = 4*LDA bytes; previously wrote 4x too far -> OOB smem).
// 128 CTAs x 256 threads, clusters of 4 = (gate, K-chunk), rank = tile.
// Threads 0-127 <-> batches 0-31; threads 128-255 <-> batches 32-63. Each
// warp-group runs the full pipeline independently (named barriers, own
// counters, own act slab + DSMEM mbarrier). Waits in one group hide behind
// the other group's FFMA2 compute.

#define NCTA 128
#define NTHR 256

typedef unsigned long long u64;

// shared layout (float offsets)
#define OFF_W1   0                 // 192 x 16
#define OFF_B1   3072              // 16
#define OFF_W2   3088              // 64 x 128 -> ends 11280
#define OFF_X    11280             // [2 wg][2 par][32 b][68]
#define LDXR     68
#define XSLAB    2176              // 32*68
#define OFF_H    19984             // [2 wg][32 b][132]
#define LDHR     132
#define HSLAB    4224
#define OFF_ACT  28432             // [2 wg][2 par][64 c][36]  (act, k-major)
#define LDA      36
#define ASLAB    2304              // 64*36
#define OFF_MBAR 37648             // 2 x u64
#define SMEM_FLOATS 37664
#define SMEM_BYTES  (SMEM_FLOATS * 4)   // 150656 B -> 1 CTA/SM

__device__ float g_hbuf[2][2][32 * 512];          // [wg][parity][b][c]
__device__ float g_part[2][2][NCTA * 32 * 128];   // [wg][parity][cta][b][cl]
__device__ unsigned g_pcnt[8 * 64];               // (wg*4+rank)*64, 256B apart
__device__ unsigned g_hcnt[8 * 64];

static __device__ __forceinline__ u64 pk2(float v) {
    u64 r; asm("mov.b64 %0, {%1, %1};" : "=l"(r) : "f"(v)); return r;
}
static __device__ __forceinline__ void unp2(u64 v, float& lo, float& hi) {
    asm("mov.b64 {%0, %1}, %2;" : "=f"(lo), "=f"(hi) : "l"(v));
}
static __device__ __forceinline__ void fma2(u64& d, u64 a, u64 b) {
    asm("fma.rn.f32x2 %0, %1, %2, %0;" : "+l"(d) : "l"(a), "l"(b));
}
static __device__ __forceinline__ float sigf(float x)  { return 1.0f / (1.0f + __expf(-x)); }
static __device__ __forceinline__ float tanhe(float x) {
    float e = __expf(2.0f * x);
    return 1.0f - 2.0f / (e + 1.0f);
}
static __device__ __forceinline__ unsigned ldacq(const unsigned* p) {
    unsigned v;
    asm volatile("ld.acquire.gpu.global.u32 %0, [%1];" : "=r"(v) : "l"(p) : "memory");
    return v;
}
static __device__ __forceinline__ void redrel(unsigned* p) {
    asm volatile("red.release.gpu.global.add.u32 [%0], 1;" :: "l"(p) : "memory");
}
static __device__ __forceinline__ uint32_t smem_u32(const void* p) {
    uint32_t a;
    asm("{ .reg .u64 t; cvta.to.shared.u64 t, %1; cvt.u32.u64 %0, t; }" : "=r"(a) : "l"(p));
    return a;
}
static __device__ __forceinline__ uint32_t mapa_rank(uint32_t addr, int rank) {
    uint32_t r;
    asm("mapa.shared::cluster.u32 %0, %1, %2;" : "=r"(r) : "r"(addr), "r"(rank));
    return r;
}
static __device__ __forceinline__ void st_cluster(uint32_t addr, float v) {
    asm volatile("st.shared::cluster.f32 [%0], %1;" :: "r"(addr), "f"(v) : "memory");
}
static __device__ __forceinline__ void mbar_arrive_cluster(uint32_t addr) {
    asm volatile("mbarrier.arrive.release.cluster.shared::cluster.b64 _, [%0];"
                 :: "r"(addr) : "memory");
}
static __device__ __forceinline__ void mbar_wait(uint32_t addr, uint32_t parity) {
    uint32_t done;
    do {
        asm volatile(
            "{ .reg .pred p;\n\t"
            "mbarrier.try_wait.parity.acquire.cluster.shared::cta.b64 p, [%1], %2;\n\t"
            "selp.b32 %0, 1, 0, p; }"
            : "=r"(done) : "r"(addr), "r"(parity) : "memory");
    } while (!done);
}
static __device__ __forceinline__ void cpasync16(uint32_t dst, const float* src) {
    asm volatile("cp.async.cg.shared.global [%0], [%1], 16;" :: "r"(dst), "l"(src) : "memory");
}
#define CP_COMMIT() asm volatile("cp.async.commit_group;" ::: "memory")
#define CP_WAIT0()  asm volatile("cp.async.wait_group 0;" ::: "memory")
#define CP_WAIT1()  asm volatile("cp.async.wait_group 1;" ::: "memory")
#define CP_WAIT2()  asm volatile("cp.async.wait_group 2;" ::: "memory")

static __device__ __forceinline__ void wgbar(int wg) {
    asm volatile("bar.sync %0, 128;" :: "r"(1 + wg) : "memory");
}

__global__ void zero_kernel() {
    int i = blockIdx.x * blockDim.x + threadIdx.x;
    int n = blockDim.x * gridDim.x;
    for (int j = i; j < 4 * 16384; j += n) ((float*)g_hbuf)[j] = 0.0f;
    for (int j = i; j < 8 * 64; j += n) { g_pcnt[j] = 0u; g_hcnt[j] = 0u; }
}

__global__ void __launch_bounds__(NTHR, 1) __cluster_dims__(4, 1, 1)
slstm_kernel(const float* __restrict__ x,       // (64, 512, 256)
             const float* __restrict__ Ws,      // (4, 64, 512)
             const float* __restrict__ Us,      // (4, 128, 512)
             const float* __restrict__ biases,  // (4, 512)
             const float* __restrict__ Wc,      // (512, 2048)
             const float* __restrict__ bc,      // (2048,)
             float* __restrict__ out)           // hseq | h_t | c_t
{
    extern __shared__ float sm[];
    float* sW1  = sm + OFF_W1;
    float* sB1  = sm + OFF_B1;
    float* sW2  = sm + OFF_W2;

    const int tid  = threadIdx.x;
    const int wg   = tid >> 7;         // warp-group = batch group
    const int wtid = tid & 127;
    const int cta  = blockIdx.x;
    const int rank = cta & 3;
    const int clu  = cta >> 2;         // 0..31
    const int g2   = clu >> 3;         // gate
    const int kc   = clu & 7;          // connector K-chunk
    const int s1   = kc >> 1;          // input slice
    const int wcol0 = g2 * 128 + (kc & 1) * 64 + rank * 16;
    const int B0   = wg * 32;          // group batch base

    float* sXg  = sm + OFF_X + wg * 2 * XSLAB;    // [par][32][68]
    float* sHg  = sm + OFF_H + wg * HSLAB;        // [32][132]
    float* sAg  = sm + OFF_ACT + wg * 2 * ASLAB;  // [par][64][36]

    // P1 role: 1 local batch x 4 cols
    const int pab = wtid >> 2;          // 0..31
    const int pac = wtid & 3;
    // P2 role: 4 local batches x 8 cols
    const int b20 = (wtid & 7) * 4;     // 0..28
    const int cg2 = wtid >> 3;          // 0..15
    // P3 role: local batch = clu, col = wtid
    const int colg = rank * 128 + wtid;

    // ---- persistent weights (both WGs cooperate) ----
    for (int i = tid; i < 192 * 16; i += NTHR) {
        int k = i >> 4, c = i & 15;
        sW1[i] = (k < 64) ? Ws[s1 * (64 * 512) + k * 512 + wcol0 + c]
                          : Us[s1 * (128 * 512) + (k - 64) * 512 + wcol0 + c];
    }
    if (tid < 16) sB1[tid] = biases[s1 * 512 + wcol0 + tid];
    for (int i = tid; i < 64 * 128; i += NTHR) {
        int k = i >> 7, c = i & 127;
        sW2[k * 128 + c] = Wc[(kc * 64 + k) * 2048 + g2 * 512 + rank * 128 + c];
    }

    const float bci = bc[colg];
    const float bcf = bc[512 + colg];
    const float bcg = bc[1024 + colg];
    const float bco = bc[1536 + colg];
    float creg = 0.0f, hlast = 0.0f;

    const uint32_t xg_u32 = smem_u32(sXg);
    const uint32_t hg_u32 = smem_u32(sHg);
    const uint32_t ag_u32 = smem_u32(sAg);
    const uint32_t mb_u32 = smem_u32(sm + OFF_MBAR) + wg * 8;
    uint32_t peerAct[4], peerMbar[4];
    #pragma unroll
    for (int r = 0; r < 4; ++r) {
        peerAct[r]  = mapa_rank(ag_u32, r);
        peerMbar[r] = mapa_rank(mb_u32, r);
    }

    if (tid == 0) {
        uint32_t mb = smem_u32(sm + OFF_MBAR);
        asm volatile("mbarrier.init.shared.b64 [%0], 512;" :: "r"(mb) : "memory");
        asm volatile("mbarrier.init.shared.b64 [%0], 512;" :: "r"(mb + 8) : "memory");
    }
    __syncthreads();
    asm volatile("barrier.cluster.arrive.aligned;" ::: "memory");
    asm volatile("barrier.cluster.wait.aligned;" ::: "memory");

    // stage x(t=0) into parity 0
    {
        #pragma unroll
        for (int j = 0; j < 4; ++j) {
            int lin = wtid + 128 * j;          // 0..511
            int b = lin >> 4, q = lin & 15;
            cpasync16(xg_u32 + (b * LDXR + q * 4) * 4,
                      &x[(B0 + b) * (512 * 256) + s1 * 64 + q * 4]);
        }
        CP_COMMIT();
        CP_WAIT0();
    }
    wgbar(wg);

    for (int t = 0; t < 512; ++t) {
        const int p  = t & 1;
        const int pn = p ^ 1;

        // --- (1) wait h-flag ---
        if (wtid == 0) {
            const unsigned need = 32u * (unsigned)t;
            while (ldacq(&g_hcnt[(wg * 4 + s1) * 64]) < need) {}
        }
        wgbar(wg);

        // --- (2) commit h group (older), then x(t+1) group (newer) ---
        {
            const float* hb = g_hbuf[wg][p];
            #pragma unroll
            for (int j = 0; j < 8; ++j) {
                int lin = wtid + 128 * j;      // 0..1023
                int b = lin >> 5, q = lin & 31;
                cpasync16(hg_u32 + (b * LDHR + q * 4) * 4,
                          &hb[b * 512 + s1 * 128 + q * 4]);
            }
        }
        CP_COMMIT();
        if (t + 1 < 512) {
            #pragma unroll
            for (int j = 0; j < 4; ++j) {
                int lin = wtid + 128 * j;
                int b = lin >> 4, q = lin & 15;
                cpasync16(xg_u32 + (pn * XSLAB + b * LDXR + q * 4) * 4,
                          &x[(B0 + b) * (512 * 256) + (t + 1) * 256 + s1 * 64 + q * 4]);
            }
        }
        CP_COMMIT();

        // --- (3) x(t) resident; P1 x-part ---
        CP_WAIT2();
        wgbar(wg);
        u64 acc0 = 0ULL, acc1 = 0ULL;
        {
            const float* ap = sXg + p * XSLAB + pab * LDXR;
            const float* wp = sW1 + pac * 4;
            #pragma unroll 8
            for (int k = 0; k < 64; ++k) {
                const ulonglong2 w = *reinterpret_cast<const ulonglong2*>(wp + k * 16);
                const u64 a = pk2(ap[k]);
                fma2(acc0, a, w.x);
                fma2(acc1, a, w.y);
            }
        }

        // --- (4) h resident; P1 h-part + activation ---
        CP_WAIT1();
        wgbar(wg);
        float v0, v1, v2, v3;
        {
            const float* ap = sHg + pab * LDHR;
            const float* wp = sW1 + pac * 4;
            #pragma unroll 8
            for (int k = 0; k < 128; ++k) {
                const ulonglong2 w = *reinterpret_cast<const ulonglong2*>(wp + (64 + k) * 16);
                const u64 a = pk2(ap[k]);
                fma2(acc0, a, w.x);
                fma2(acc1, a, w.y);
            }
            unp2(acc0, v0, v1);
            unp2(acc1, v2, v3);
            v0 += sB1[pac * 4 + 0];
            v1 += sB1[pac * 4 + 1];
            v2 += sB1[pac * 4 + 2];
            v3 += sB1[pac * 4 + 3];
            if (g2 == 2) { v0 = tanhe(v0); v1 = tanhe(v1); v2 = tanhe(v2); v3 = tanhe(v3); }
            else         { v0 = sigf(v0);  v1 = sigf(v1);  v2 = sigf(v2);  v3 = sigf(v3);  }
        }

        // --- (5) act publish to all 4 ranks + mbarrier arrives ---
        // one column = LDA floats = 4*LDA bytes (FIX: was 4x too large)
        {
            const int lc = rank * 16 + pac * 4;
            const uint32_t off = (uint32_t)(p * ASLAB + lc * LDA + pab) * 4;
            #pragma unroll
            for (int r = 0; r < 4; ++r) {
                const uint32_t ra = peerAct[r] + off;
                st_cluster(ra,               v0);
                st_cluster(ra + 4 * LDA,     v1);
                st_cluster(ra + 8 * LDA,     v2);
                st_cluster(ra + 12 * LDA,    v3);
            }
            #pragma unroll
            for (int r = 0; r < 4; ++r) mbar_arrive_cluster(peerMbar[r]);
        }
        mbar_wait(mb_u32, (uint32_t)(t & 1));

        // --- (6) P2 connector GEMM (4 local b x 8 cols per thread) ---
        {
            u64 acc[4][4];
            #pragma unroll
            for (int i = 0; i < 4; ++i)
                #pragma unroll
                for (int j = 0; j < 4; ++j) acc[i][j] = 0ULL;
            const float* ab = sAg + p * ASLAB;
            const float* wb = sW2 + cg2 * 8;
            #pragma unroll 4
            for (int k = 0; k < 64; ++k) {
                const float4 a4 = *reinterpret_cast<const float4*>(&ab[k * LDA + b20]);
                const ulonglong2 wA = *reinterpret_cast<const ulonglong2*>(&wb[k * 128]);
                const ulonglong2 wB = *reinterpret_cast<const ulonglong2*>(&wb[k * 128 + 4]);
                const u64 a0 = pk2(a4.x);
                const u64 a1 = pk2(a4.y);
                const u64 a2 = pk2(a4.z);
                const u64 a3 = pk2(a4.w);
                fma2(acc[0][0], a0, wA.x); fma2(acc[0][1], a0, wA.y);
                fma2(acc[0][2], a0, wB.x); fma2(acc[0][3], a0, wB.y);
                fma2(acc[1][0], a1, wA.x); fma2(acc[1][1], a1, wA.y);
                fma2(acc[1][2], a1, wB.x); fma2(acc[1][3], a1, wB.y);
                fma2(acc[2][0], a2, wA.x); fma2(acc[2][1], a2, wA.y);
                fma2(acc[2][2], a2, wB.x); fma2(acc[2][3], a2, wB.y);
                fma2(acc[3][0], a3, wA.x); fma2(acc[3][1], a3, wA.y);
                fma2(acc[3][2], a3, wB.x); fma2(acc[3][3], a3, wB.y);
            }
            float* pp = g_part[wg][p] + cta * 4096 + cg2 * 8;
            #pragma unroll
            for (int i = 0; i < 4; ++i) {
                float q0, q1, q2, q3, q4, q5, q6, q7;
                unp2(acc[i][0], q0, q1); unp2(acc[i][1], q2, q3);
                unp2(acc[i][2], q4, q5); unp2(acc[i][3], q6, q7);
                float4* d = reinterpret_cast<float4*>(pp + (b20 + i) * 128);
                __stcg(d,     make_float4(q0, q1, q2, q3));
                __stcg(d + 1, make_float4(q4, q5, q6, q7));
            }
        }
        wgbar(wg);
        if (wtid == 0) {
            redrel(&g_pcnt[(wg * 4 + rank) * 64]);
            const unsigned need = 32u * (unsigned)(t + 1);
            while (ldacq(&g_pcnt[(wg * 4 + rank) * 64]) < need) {}
        }
        wgbar(wg);

        // --- (7) P3: one (batch=clu, col=wtid) per thread ---
        {
            float a0 = bci, a1 = bcf, a2 = bcg, a3 = bco;
            const float* gp = g_part[wg][p] + clu * 128 + wtid;
            #pragma unroll
            for (int q = 0; q < 8; ++q) {
                a0 += __ldcg(gp + (( 0 + q) * 4 + rank) * 4096);
                a1 += __ldcg(gp + (( 8 + q) * 4 + rank) * 4096);
                a2 += __ldcg(gp + ((16 + q) * 4 + rank) * 4096);
                a3 += __ldcg(gp + ((24 + q) * 4 + rank) * 4096);
            }
            const float iv = sigf(a0);
            const float fv = sigf(a1);
            const float gv = tanhe(a2);
            const float ov = sigf(a3);
            creg = fv * creg + iv * gv;
            const float hn = ov * tanhe(creg);
            hlast = hn;
            __stcg(&g_hbuf[wg][pn][clu * 512 + colg], hn);
            wgbar(wg);
            if (wtid == 0) redrel(&g_hcnt[(wg * 4 + rank) * 64]);
            out[(B0 + clu) * (512 * 512) + t * 512 + colg] = hn;
        }
    }

    out[16777216 + (B0 + clu) * 512 + colg] = hlast;
    out[16777216 + 32768 + (B0 + clu) * 512 + colg] = creg;

    __syncthreads();
    asm volatile("barrier.cluster.arrive.aligned;" ::: "memory");
    asm volatile("barrier.cluster.wait.aligned;" ::: "memory");
}

extern "C" void kernel_launch(void* const* d_in, const int* in_sizes, int n_in,
                              void* d_out, int out_size) {
    const float* x      = (const float*)d_in[0];
    const float* Ws     = (const float*)d_in[1];
    const float* Us     = (const float*)d_in[2];
    const float* biases = (const float*)d_in[3];
    const float* Wc     = (const float*)d_in[4];
    const float* bc     = (const float*)d_in[5];
    float* out = (float*)d_out;
    (void)in_sizes; (void)n_in; (void)out_size;

    zero_kernel<<<32, 256>>>();
    cudaFuncSetAttribute(slstm_kernel, cudaFuncAttributeMaxDynamicSharedMemorySize,
                         SMEM_BYTES);
    slstm_kernel<<<NCTA, NTHR, SMEM_BYTES>>>(x, Ws, Us, biases, Wc, bc, out);
}